// round 5
// baseline (speedup 1.0000x reference)
#include <cuda_runtime.h>
#include <cuda_bf16.h>

// ALiBi bias materialization:
//   out[z, i, j] = -slopes[z % 16] * |i - j|,  z in [0,64), i,j in [0,2048)
// Output 1 GiB fp32 -> pure HBM-write-bound (measured wall ~7.0 TB/s).
//
// R5: persistent grid. 1184 CTAs (148 SMs x 8 resident blocks) grid-stride
// over 32768 4-row tiles -> no wave transitions, perfectly balanced tail
// (each CTA does 27-28 tiles). Store path unchanged (2x STG.128 per row,
// proven at the DRAM-write wall).

#define S        2048
#define NUM_H    16
#define Z_TOTAL  64
#define THREADS  256
#define ROWS_PER_BLOCK 4
#define NUM_TILES ((Z_TOTAL * S) / ROWS_PER_BLOCK)   // 32768
#define PERSISTENT_BLOCKS (148 * 8)                   // 1184

__global__ __launch_bounds__(THREADS)
void alibi_kernel(const float* __restrict__ slopes, float* __restrict__ out) {
    const unsigned t  = threadIdx.x;
    const unsigned jA = t * 4u;
    const unsigned jB = jA + 1024u;
    const float fjA = (float)jA;
    const float fjB = (float)jB;

    for (unsigned tile = blockIdx.x; tile < NUM_TILES; tile += gridDim.x) {
        const unsigned row0 = tile * ROWS_PER_BLOCK;
        const unsigned h    = (row0 >> 11) & (NUM_H - 1);   // uniform in block
        const float neg_slope = -__ldg(&slopes[h]);

        float* base = out + (size_t)row0 * S;

#pragma unroll
        for (int r = 0; r < ROWS_PER_BLOCK; r++) {
            const float fi = (float)((row0 + r) & (S - 1));

            float4 a, b;
            a.x = neg_slope * fabsf(fi - fjA);
            a.y = neg_slope * fabsf(fi - (fjA + 1.0f));
            a.z = neg_slope * fabsf(fi - (fjA + 2.0f));
            a.w = neg_slope * fabsf(fi - (fjA + 3.0f));
            b.x = neg_slope * fabsf(fi - fjB);
            b.y = neg_slope * fabsf(fi - (fjB + 1.0f));
            b.z = neg_slope * fabsf(fi - (fjB + 2.0f));
            b.w = neg_slope * fabsf(fi - (fjB + 3.0f));

            float* rowp = base + (size_t)r * S;
            reinterpret_cast<float4*>(rowp)[t]        = a;
            reinterpret_cast<float4*>(rowp + 1024)[t] = b;
        }
    }
}

extern "C" void kernel_launch(void* const* d_in, const int* in_sizes, int n_in,
                              void* d_out, int out_size) {
    const float* slopes = (const float*)d_in[0];
    float* out = (float*)d_out;

    alibi_kernel<<<PERSISTENT_BLOCKS, THREADS>>>(slopes, out);
}

// round 6
// speedup vs baseline: 1.2101x; 1.2101x over previous
#include <cuda_runtime.h>
#include <cuda_bf16.h>

// ALiBi bias materialization:
//   out[z, i, j] = -slopes[z % 16] * |i - j|
//   z in [0, 64)  (batch_size=4 * num_heads=16, h = z % 16), i, j in [0, 2048)
// Output: 64 * 2048 * 2048 fp32 = 1 GiB -> pure HBM-write-bound.
//
// FINAL (revert to R1, best measured 147.36us = ~7.0 TB/s, the DRAM-write
// wall on this part). Verified non-levers: fatter blocks (R2), streaming
// .cs stores (R3), 256-bit v8.f32 stores (R4) — all neutral at 85.5% DRAM
// busy; persistent grid (R5) regressed 21% by serializing store issue.
// Tiny blocks + deep oversubscription keep the LTS/DRAM write queues
// saturated via the HW CTA scheduler.

#define S        2048
#define NUM_H    16
#define BATCH    4
#define Z_TOTAL  (BATCH * NUM_H)          // 64
#define HALF_ROW 1024                     // floats per block
#define THREADS  256                      // 256 threads * float4 = 1024 floats

__global__ __launch_bounds__(THREADS)
void alibi_kernel(const float* __restrict__ slopes, float* __restrict__ out) {
    // blockIdx.x = row * 2 + half;  rows = Z_TOTAL * S = 131072
    const unsigned bx   = blockIdx.x;
    const unsigned row  = bx >> 1;
    const unsigned half = bx & 1u;
    const unsigned i    = row & (S - 1);
    const unsigned h    = (row >> 11) & (NUM_H - 1);

    const float neg_slope = -__ldg(&slopes[h]);
    const float fi = (float)i;

    const unsigned j0 = half * HALF_ROW + threadIdx.x * 4u;
    const float fj = (float)j0;

    float4 v;
    v.x = neg_slope * fabsf(fi - fj);
    v.y = neg_slope * fabsf(fi - (fj + 1.0f));
    v.z = neg_slope * fabsf(fi - (fj + 2.0f));
    v.w = neg_slope * fabsf(fi - (fj + 3.0f));

    float4* dst = reinterpret_cast<float4*>(out + (size_t)row * S + j0);
    *dst = v;
}

extern "C" void kernel_launch(void* const* d_in, const int* in_sizes, int n_in,
                              void* d_out, int out_size) {
    const float* slopes = (const float*)d_in[0];
    float* out = (float*)d_out;

    const unsigned grid = Z_TOTAL * S * 2;   // 262144 blocks
    alibi_kernel<<<grid, THREADS>>>(slopes, out);
}